// round 8
// baseline (speedup 1.0000x reference)
#include <cuda_runtime.h>
#include <cuda_bf16.h>
#include <math_constants.h>

// ExactScoreNetwork: out[b,d] = sqrt(1-e_b) * sum_k p_bk * (x_bd - a_b*c_kd) / v_bkd
//   e = exp(-Beta(t)), a = sqrt(e), v = 1 + e*(s^2 - 1)
//   p_bk = softmax_k( -0.5*sum_d diff^2/v - 128*sum_d ln v + ln w_k )
// (the 128*D*ln(2pi) constant is softmax-invariant and dropped)

constexpr int K_COMP = 128;
constexpr int D_DIM  = 256;
constexpr int R_ROWS = 4;

__device__ __forceinline__ float frcp(float x){ float r; asm("rcp.approx.ftz.f32 %0, %1;" : "=f"(r) : "f"(x)); return r; }
__device__ __forceinline__ float flg2(float x){ float r; asm("lg2.approx.ftz.f32 %0, %1;" : "=f"(r) : "f"(x)); return r; }
__device__ __forceinline__ float fex2(float x){ float r; asm("ex2.approx.ftz.f32 %0, %1;" : "=f"(r) : "f"(x)); return r; }
__device__ __forceinline__ float fexp_fast(float x){ return fex2(x * 1.4426950408889634f); }

// accurate-ish log2: split exponent, lg2.approx on mantissa in [1,2)
__device__ __forceinline__ float log2_acc(float p){
    int b = __float_as_int(p);
    float m = __int_as_float((b & 0x007FFFFF) | 0x3F800000);
    return (float)((b >> 23) - 127) + flg2(m);
}

__global__ void __launch_bounds__(32)
score_kernel(const float* __restrict__ x, const float* __restrict__ t,
             const float* __restrict__ centers, const float* __restrict__ stds,
             const float* __restrict__ weights, float* __restrict__ out)
{
    const int lane = threadIdx.x;
    const int b0   = blockIdx.x * R_ROWS;

    float ev[R_ROWS], na[R_ROWS], osc[R_ROWS];
    float xr[R_ROWS][8], acc[R_ROWS][8], mx[R_ROWS], den[R_ROWS];

    #pragma unroll
    for (int r = 0; r < R_ROWS; r++) {
        float tt = t[b0 + r];
        float Bt = fmaf(9.95f, tt * tt, 0.1f * tt);   // Beta(t) = 0.1 t + 9.95 t^2
        float e  = expf(-Bt);                          // accurate: matters for 1-e at small t
        ev[r]  = e;
        na[r]  = -sqrtf(e);                            // -a
        osc[r] = sqrtf(fmaxf(1.0f - e, 0.0f));
        const float4* xp = reinterpret_cast<const float4*>(x + (size_t)(b0 + r) * D_DIM + lane * 8);
        float4 x0 = xp[0], x1 = xp[1];
        xr[r][0]=x0.x; xr[r][1]=x0.y; xr[r][2]=x0.z; xr[r][3]=x0.w;
        xr[r][4]=x1.x; xr[r][5]=x1.y; xr[r][6]=x1.z; xr[r][7]=x1.w;
        #pragma unroll
        for (int j = 0; j < 8; j++) acc[r][j] = 0.0f;
        mx[r]  = -CUDART_INF_F;
        den[r] = 0.0f;
    }

    #pragma unroll 1
    for (int k = 0; k < K_COMP; k++) {
        const float4* cp = reinterpret_cast<const float4*>(centers + (size_t)k * D_DIM + lane * 8);
        const float4* sp = reinterpret_cast<const float4*>(stds    + (size_t)k * D_DIM + lane * 8);
        float4 c0 = __ldg(cp), c1 = __ldg(cp + 1);
        float4 s0 = __ldg(sp), s1 = __ldg(sp + 1);
        float c[8]  = {c0.x,c0.y,c0.z,c0.w,c1.x,c1.y,c1.z,c1.w};
        float sv[8] = {s0.x,s0.y,s0.z,s0.w,s1.x,s1.y,s1.z,s1.w};
        float u[8];
        #pragma unroll
        for (int j = 0; j < 8; j++) u[j] = fmaf(sv[j], sv[j], -1.0f);   // s^2 - 1

        float lw = __logf(__ldg(weights + k));

        float g[R_ROWS][8], qv[R_ROWS], Lv[R_ROWS];
        #pragma unroll
        for (int r = 0; r < R_ROWS; r++) {
            float q = 0.0f, prod = 1.0f;
            #pragma unroll
            for (int j = 0; j < 8; j++) {
                float v  = fmaf(ev[r], u[j], 1.0f);   // in [0.25, 1]
                float rv = frcp(v);
                float d  = fmaf(na[r], c[j], xr[r][j]);
                float gg = d * rv;
                q = fmaf(d, gg, q);                    // sum diff^2 / v
                prod *= v;                             // chunk product for log-det
                g[r][j] = gg;                          // diff / v (grad piece)
            }
            qv[r] = q;
            Lv[r] = log2_acc(prod);
        }

        // warp reductions over the D dimension (2 values per row)
        #pragma unroll
        for (int off = 16; off >= 1; off >>= 1) {
            #pragma unroll
            for (int r = 0; r < R_ROWS; r++) {
                qv[r] += __shfl_xor_sync(0xffffffffu, qv[r], off);
                Lv[r] += __shfl_xor_sync(0xffffffffu, Lv[r], off);
            }
        }

        #pragma unroll
        for (int r = 0; r < R_ROWS; r++) {
            // lp = -0.5*q - 128*ln2*sum(log2 v) + ln w   (128*ln2 = 88.7228391...)
            float lp = fmaf(-0.5f, qv[r], fmaf(-88.72283911167299f, Lv[r], lw));
            if (lp > mx[r]) {                 // warp-uniform branch (lp is reduced)
                float sc = fexp_fast(mx[r] - lp);   // exp(-inf)=0 on first hit
                den[r] = fmaf(den[r], sc, 1.0f);
                #pragma unroll
                for (int j = 0; j < 8; j++) acc[r][j] = fmaf(acc[r][j], sc, g[r][j]);
                mx[r] = lp;
            } else {
                float p = fexp_fast(lp - mx[r]);
                den[r] += p;
                #pragma unroll
                for (int j = 0; j < 8; j++) acc[r][j] = fmaf(p, g[r][j], acc[r][j]);
            }
        }
    }

    #pragma unroll
    for (int r = 0; r < R_ROWS; r++) {
        float s = osc[r] * frcp(den[r]);
        float4 o0, o1;
        o0.x = acc[r][0]*s; o0.y = acc[r][1]*s; o0.z = acc[r][2]*s; o0.w = acc[r][3]*s;
        o1.x = acc[r][4]*s; o1.y = acc[r][5]*s; o1.z = acc[r][6]*s; o1.w = acc[r][7]*s;
        float4* op = reinterpret_cast<float4*>(out + (size_t)(b0 + r) * D_DIM + lane * 8);
        op[0] = o0; op[1] = o1;
    }
}

extern "C" void kernel_launch(void* const* d_in, const int* in_sizes, int n_in,
                              void* d_out, int out_size)
{
    const float* x       = (const float*)d_in[0];   // [B, 256]
    const float* t       = (const float*)d_in[1];   // [B]
    const float* centers = (const float*)d_in[2];   // [128, 256]
    const float* stds    = (const float*)d_in[3];   // [128, 256]
    const float* weights = (const float*)d_in[4];   // [128]
    float* out = (float*)d_out;                      // [B, 256]

    int B = in_sizes[1];                             // t element count
    dim3 grid(B / R_ROWS), block(32);
    score_kernel<<<grid, block>>>(x, t, centers, stds, weights, out);
}

// round 9
// speedup vs baseline: 1.3350x; 1.3350x over previous
#include <cuda_runtime.h>
#include <cuda_bf16.h>
#include <math_constants.h>

// ExactScoreNetwork: out[b,d] = sqrt(1-e_b) * sum_k p_bk * (x_bd - a_b*c_kd) / v_bkd
//   e = exp(-Beta(t)), a = sqrt(e), v = 1 + e*(s^2 - 1)
//   p_bk = softmax_k( -0.5*sum_d diff^2/v - 128*sum_d ln v + ln w_k )
// All softmax bookkeeping done in log2 domain (ex2.approx, no log2e multiplies).

constexpr int K_COMP = 128;
constexpr int D_DIM  = 256;
constexpr int R_ROWS = 2;          // rows per warp; grid = B/R = 2048 warps (occupancy!)

__device__ __forceinline__ float frcp(float x){ float r; asm("rcp.approx.ftz.f32 %0, %1;" : "=f"(r) : "f"(x)); return r; }
__device__ __forceinline__ float flg2(float x){ float r; asm("lg2.approx.ftz.f32 %0, %1;" : "=f"(r) : "f"(x)); return r; }
__device__ __forceinline__ float fex2(float x){ float r; asm("ex2.approx.ftz.f32 %0, %1;" : "=f"(r) : "f"(x)); return r; }

// accurate-ish log2: split exponent, lg2.approx on mantissa in [1,2)
__device__ __forceinline__ float log2_acc(float p){
    int b = __float_as_int(p);
    float m = __int_as_float((b & 0x007FFFFF) | 0x3F800000);
    return (float)((b >> 23) - 127) + flg2(m);
}

__global__ void __launch_bounds__(32)
score_kernel(const float* __restrict__ x, const float* __restrict__ t,
             const float* __restrict__ centers, const float* __restrict__ stds,
             const float* __restrict__ weights, float* __restrict__ out)
{
    const int lane = threadIdx.x;
    const int b0   = blockIdx.x * R_ROWS;

    float ev[R_ROWS], na[R_ROWS], osc[R_ROWS];
    float xr[R_ROWS][8], acc[R_ROWS][8], mx[R_ROWS], den[R_ROWS];

    #pragma unroll
    for (int r = 0; r < R_ROWS; r++) {
        float tt = t[b0 + r];
        float Bt = fmaf(9.95f, tt * tt, 0.1f * tt);   // Beta(t) = 0.1 t + 9.95 t^2
        float e  = expf(-Bt);                          // accurate: matters for 1-e at small t
        ev[r]  = e;
        na[r]  = -sqrtf(e);                            // -a
        osc[r] = sqrtf(fmaxf(1.0f - e, 0.0f));
        const float4* xp = reinterpret_cast<const float4*>(x + (size_t)(b0 + r) * D_DIM + lane * 8);
        float4 x0 = xp[0], x1 = xp[1];
        xr[r][0]=x0.x; xr[r][1]=x0.y; xr[r][2]=x0.z; xr[r][3]=x0.w;
        xr[r][4]=x1.x; xr[r][5]=x1.y; xr[r][6]=x1.z; xr[r][7]=x1.w;
        #pragma unroll
        for (int j = 0; j < 8; j++) acc[r][j] = 0.0f;
        mx[r]  = -CUDART_INF_F;                        // log2-domain running max
        den[r] = 0.0f;
    }

    #pragma unroll 1
    for (int k = 0; k < K_COMP; k++) {
        const float4* cp = reinterpret_cast<const float4*>(centers + (size_t)k * D_DIM + lane * 8);
        const float4* sp = reinterpret_cast<const float4*>(stds    + (size_t)k * D_DIM + lane * 8);
        float4 c0 = __ldg(cp), c1 = __ldg(cp + 1);
        float4 s0 = __ldg(sp), s1 = __ldg(sp + 1);
        float c[8]  = {c0.x,c0.y,c0.z,c0.w,c1.x,c1.y,c1.z,c1.w};
        float sv[8] = {s0.x,s0.y,s0.z,s0.w,s1.x,s1.y,s1.z,s1.w};
        float u[8];
        #pragma unroll
        for (int j = 0; j < 8; j++) u[j] = fmaf(sv[j], sv[j], -1.0f);   // s^2 - 1

        float lw2 = log2_acc(__ldg(weights + k));      // log2(w_k)

        float g[R_ROWS][8], z[R_ROWS];
        #pragma unroll
        for (int r = 0; r < R_ROWS; r++) {
            float q = 0.0f, prod = 1.0f;
            #pragma unroll
            for (int j = 0; j < 8; j++) {
                float v  = fmaf(ev[r], u[j], 1.0f);   // in [0.25, 1]
                float rv = frcp(v);
                float d  = fmaf(na[r], c[j], xr[r][j]);
                float gg = d * rv;
                q = fmaf(d, gg, q);                    // sum diff^2 / v
                prod *= v;                             // chunk product for log-det
                g[r][j] = gg;                          // diff / v (grad piece)
            }
            // per-lane combined log2-domain partial:
            //   z = -0.5*log2e * q  - 128 * log2(prod_chunk)
            z[r] = fmaf(-0.72134752044448170f, q, -128.0f * log2_acc(prod));
        }

        // ONE fused warp reduction per row (5 shfl + 5 add)
        #pragma unroll
        for (int off = 16; off >= 1; off >>= 1) {
            #pragma unroll
            for (int r = 0; r < R_ROWS; r++)
                z[r] += __shfl_xor_sync(0xffffffffu, z[r], off);
        }

        // branchless online softmax update (log2 domain)
        #pragma unroll
        for (int r = 0; r < R_ROWS; r++) {
            float lp = z[r] + lw2;
            float mn = fmaxf(mx[r], lp);
            float sc = fex2(mx[r] - lp > 0.0f ? 0.0f : mx[r] - lp); // guard not needed, but cheap via fmax:
            sc = fex2(fminf(mx[r] - mn, 0.0f));        // = 1 when mx>=lp; ex2(-inf)=0 on first k
            float p  = fex2(lp - mn);                  // <= 1
            den[r] = fmaf(den[r], sc, p);
            #pragma unroll
            for (int j = 0; j < 8; j++)
                acc[r][j] = fmaf(acc[r][j], sc, p * g[r][j]);
            mx[r] = mn;
        }
    }

    #pragma unroll
    for (int r = 0; r < R_ROWS; r++) {
        float s = osc[r] * frcp(den[r]);
        float4 o0, o1;
        o0.x = acc[r][0]*s; o0.y = acc[r][1]*s; o0.z = acc[r][2]*s; o0.w = acc[r][3]*s;
        o1.x = acc[r][4]*s; o1.y = acc[r][5]*s; o1.z = acc[r][6]*s; o1.w = acc[r][7]*s;
        float4* op = reinterpret_cast<float4*>(out + (size_t)(b0 + r) * D_DIM + lane * 8);
        op[0] = o0; op[1] = o1;
    }
}

extern "C" void kernel_launch(void* const* d_in, const int* in_sizes, int n_in,
                              void* d_out, int out_size)
{
    const float* x       = (const float*)d_in[0];   // [B, 256]
    const float* t       = (const float*)d_in[1];   // [B]
    const float* centers = (const float*)d_in[2];   // [128, 256]
    const float* stds    = (const float*)d_in[3];   // [128, 256]
    const float* weights = (const float*)d_in[4];   // [128]
    float* out = (float*)d_out;                      // [B, 256]

    int B = in_sizes[1];                             // t element count
    dim3 grid(B / R_ROWS), block(32);
    score_kernel<<<grid, block>>>(x, t, centers, stds, weights, out);
}